// round 2
// baseline (speedup 1.0000x reference)
#include <cuda_runtime.h>

// BALayer: reference computes, for each of N features, the rank of the
// minimum node index reachable within n_img(=16) hops in the track graph.
// Equivalent to 16 synchronous (Jacobi) rounds of min-label propagation,
// then a prefix-sum rank of self-leaders and a gather.
//
// Everything fits in one SM: labels ping-pong in shared memory (2 x 16 KB),
// edges cached in registers (8 per thread x 1024 threads = 8192 edges).
// One kernel, one block, zero global traffic in the mainloop.
//
// NOTE: harness compares the output as float32 (R1 finding: int-bit writes
// read back as denormals -> rel_err == 1.0), so the association ids are
// stored as floats.

#define NMAX 4096
#define TPB  1024
#define EPT  8   // max edges per thread (M <= TPB*EPT = 8192)

__global__ __launch_bounds__(TPB, 1)
void balayer_assoc_kernel(const int* __restrict__ tracks,   // [2, m] row-major
                          const int* __restrict__ nimg_ptr, // scalar or null
                          float* __restrict__ out,          // [n] float32
                          int n, int m)
{
    __shared__ int labA[NMAX];
    __shared__ int labB[NMAX];
    __shared__ int wsum[32];

    const int tid  = threadIdx.x;
    const int lane = tid & 31;
    const int wid  = tid >> 5;

    // ---- init labels: L0[j] = j ----
    for (int j = tid; j < n; j += TPB) labA[j] = j;

    // ---- cache this thread's edges in registers ----
    int eu[EPT], ev[EPT];
    int ne = 0;
#pragma unroll
    for (int k = 0; k < EPT; k++) {
        int e = tid + k * TPB;
        if (e < m) {
            eu[k] = tracks[e];
            ev[k] = tracks[m + e];
            ne = k + 1;
        }
    }

    int rounds = 16;
    if (nimg_ptr != nullptr) {
        int r = *nimg_ptr;                 // uniform load, all threads
        if (r >= 1 && r <= 64) rounds = r; // sanity clamp (never hang)
    }

    __syncthreads();

    // ---- Jacobi min-label propagation: exactly `rounds` hops ----
    int* cur = labA;
    int* nxt = labB;
    for (int r = 0; r < rounds; r++) {
        // nxt = cur  (self term of the min)
        for (int j = tid; j < n; j += TPB) nxt[j] = cur[j];
        __syncthreads();
        // relax edges (reads from cur only -> synchronous semantics)
#pragma unroll
        for (int k = 0; k < EPT; k++) {
            if (k < ne) {
                int u = eu[k], v = ev[k];
                int lu = cur[u], lv = cur[v];
                if (lv < lu)      atomicMin(&nxt[u], lv);
                else if (lu < lv) atomicMin(&nxt[v], lu);
                // equal labels: both atomics would be no-ops; skip.
            }
        }
        __syncthreads();
        int* t = cur; cur = nxt; nxt = t;
    }
    // cur now holds leading[j] = min index within `rounds` hops of j.

    // ---- point_id = cumsum(is_self) - 1, via a block scan ----
    const int base = tid * 4;            // contiguous 4-element chunk per thread
    int loc[4];
    int cnt = 0;
#pragma unroll
    for (int k = 0; k < 4; k++) {
        int j = base + k;
        int s = (j < n && cur[j] == j) ? 1 : 0;
        loc[k] = s;
        cnt += s;
    }

    // warp-inclusive scan of per-thread counts
    int incl = cnt;
#pragma unroll
    for (int off = 1; off < 32; off <<= 1) {
        int x = __shfl_up_sync(0xffffffffu, incl, off);
        if (lane >= off) incl += x;
    }
    if (lane == 31) wsum[wid] = incl;
    __syncthreads();
    if (wid == 0) {
        int s  = wsum[lane];
        int si = s;
#pragma unroll
        for (int off = 1; off < 32; off <<= 1) {
            int x = __shfl_up_sync(0xffffffffu, si, off);
            if (lane >= off) si += x;
        }
        wsum[lane] = si - s;             // exclusive warp offsets
    }
    __syncthreads();

    int run = wsum[wid] + (incl - cnt);  // exclusive prefix for this thread
#pragma unroll
    for (int k = 0; k < 4; k++) {
        int j = base + k;
        run += loc[k];
        if (j < n) nxt[j] = run - 1;     // point_id[j] (nxt is the free buffer)
    }
    __syncthreads();

    // ---- association[j] = point_id[leading[j]], stored as float32 ----
    for (int j = tid; j < n; j += TPB) out[j] = (float)nxt[cur[j]];
}

extern "C" void kernel_launch(void* const* d_in, const int* in_sizes, int n_in,
                              void* d_out, int out_size)
{
    // metadata order: proj_mats, feats, feat_img, feat_loc, tracks, n_img
    // Only tracks (+ n_img) matter for the output.
    const int n = out_size;                      // N = 4096

    int tracks_idx = 4;
    int nimg_idx   = -1;
    for (int i = 0; i < n_in; i++) {
        if (in_sizes[i] == 1) nimg_idx = i;      // n_img scalar, if present
    }
    if (tracks_idx >= n_in || in_sizes[tracks_idx] < 2 ||
        (in_sizes[tracks_idx] & 1)) {
        for (int i = 0; i < n_in; i++) {
            if (in_sizes[i] > n * 2 && in_sizes[i] < n * n &&
                (in_sizes[i] & 1) == 0) { tracks_idx = i; break; }
        }
    }

    const int m = in_sizes[tracks_idx] / 2;      // M = 8192

    const int* tracks = (const int*)d_in[tracks_idx];
    const int* nimg   = (nimg_idx >= 0) ? (const int*)d_in[nimg_idx] : nullptr;
    float*     out    = (float*)d_out;

    balayer_assoc_kernel<<<1, TPB>>>(tracks, nimg, out, n, m);
}

// round 4
// speedup vs baseline: 1.1611x; 1.1611x over previous
#include <cuda_runtime.h>

// BALayer: for each of N features, the rank of the minimum node index
// reachable within n_img(=16) hops in the track graph.
// = n_img synchronous (Jacobi) rounds of min-label propagation, then a
// prefix-sum rank of self-leaders and a gather. Output compared as float32.
//
// R4 structure: single block, TWO ping-pong label buffers, ONE barrier per
// round. Key invariant: labels are monotone non-increasing, so the stale
// content of nxt (= L_{r-1} >= L_r = cur) is erased for free by the copy
// step atomicMin(&nxt[j], cur[j]) — no reset phase or third buffer needed.
// Copy and relax atomics commute, so they share one phase.
// Early exit when a round fires no relaxation (fixed point => remaining
// rounds are the identity => bit-identical to running all n_img rounds).

#define NMAX 4096
#define TPB  1024
#define EPT  8          // M <= TPB*EPT = 8192
#define MAXR 64

__global__ __launch_bounds__(TPB, 1)
void balayer_assoc_kernel(const int* __restrict__ tracks,   // [2, m]
                          const int* __restrict__ nimg_ptr, // scalar or null
                          float* __restrict__ out,          // [n] float32
                          int n, int m)
{
    __shared__ int L[2][NMAX];
    __shared__ int flags[MAXR];
    __shared__ int wsum[32];

    const int tid  = threadIdx.x;
    const int lane = tid & 31;
    const int wid  = tid >> 5;

    // ---- init: both buffers = identity (valid "stale >= current" state) ----
#pragma unroll
    for (int k = 0; k < 4; k++) {
        int j = tid + k * TPB;            // stride TPB => bank = lane
        if (j < n) {
            L[0][j] = j;
            L[1][j] = j;
        }
    }
    if (tid < MAXR) flags[tid] = 0;

    // ---- cache this thread's edges in registers (coalesced LDG) ----
    int eu[EPT], ev[EPT];
    int ne = 0;
#pragma unroll
    for (int k = 0; k < EPT; k++) {
        int e = tid + k * TPB;
        if (e < m) {
            eu[k] = tracks[e];
            ev[k] = tracks[m + e];
            ne = k + 1;
        }
    }

    int rounds = 16;
    if (nimg_ptr != nullptr) {
        int r = *nimg_ptr;
        if (r >= 1 && r <= MAXR) rounds = r;
    }

    __syncthreads();

    // ---- Jacobi min-label propagation, one barrier per round ----
    int cur = 0, nxt = 1;
    for (int r = 0; r < rounds; r++) {
        // copy (self term): stale nxt content is >= cur, erased by the min
#pragma unroll
        for (int k = 0; k < 4; k++) {
            int j = tid + k * TPB;
            if (j < n) atomicMin(&L[nxt][j], L[cur][j]);
        }
        // relax edges (reads cur only -> synchronous semantics)
#pragma unroll
        for (int k = 0; k < EPT; k++) {
            if (k < ne) {
                int u = eu[k], v = ev[k];
                int lu = L[cur][u], lv = L[cur][v];
                if (lv < lu)      { atomicMin(&L[nxt][u], lv); flags[r] = 1; }
                else if (lu < lv) { atomicMin(&L[nxt][v], lu); flags[r] = 1; }
            }
        }
        __syncthreads();

        int changed = flags[r];           // broadcast LDS
        int t = cur; cur = nxt; nxt = t;
        if (!changed) break;              // fixed point: remaining rounds = id
    }
    // L[cur] holds leading[j] = min index within `rounds` hops of j.

    // ---- point_id = cumsum(is_self) - 1, block scan (runs once) ----
    const int base = tid * 4;
    int loc[4];
    int cnt = 0;
#pragma unroll
    for (int k = 0; k < 4; k++) {
        int j = base + k;
        int s = (j < n && L[cur][j] == j) ? 1 : 0;
        loc[k] = s;
        cnt += s;
    }

    int incl = cnt;
#pragma unroll
    for (int off = 1; off < 32; off <<= 1) {
        int x = __shfl_up_sync(0xffffffffu, incl, off);
        if (lane >= off) incl += x;
    }
    if (lane == 31) wsum[wid] = incl;
    __syncthreads();
    if (wid == 0) {
        int s  = wsum[lane];
        int si = s;
#pragma unroll
        for (int off = 1; off < 32; off <<= 1) {
            int x = __shfl_up_sync(0xffffffffu, si, off);
            if (lane >= off) si += x;
        }
        wsum[lane] = si - s;              // exclusive warp offsets
    }
    __syncthreads();

    int run = wsum[wid] + (incl - cnt);
#pragma unroll
    for (int k = 0; k < 4; k++) {
        int j = base + k;
        run += loc[k];
        if (j < n) L[nxt][j] = run - 1;   // point_id[j] in the free buffer
    }
    __syncthreads();

    // ---- association[j] = point_id[leading[j]], as float32 ----
#pragma unroll
    for (int k = 0; k < 4; k++) {
        int j = tid + k * TPB;
        if (j < n) out[j] = (float)L[nxt][L[cur][j]];
    }
}

extern "C" void kernel_launch(void* const* d_in, const int* in_sizes, int n_in,
                              void* d_out, int out_size)
{
    // metadata order: proj_mats, feats, feat_img, feat_loc, tracks, n_img
    const int n = out_size;                      // N = 4096

    int tracks_idx = 4;
    int nimg_idx   = -1;
    for (int i = 0; i < n_in; i++) {
        if (in_sizes[i] == 1) nimg_idx = i;
    }
    if (tracks_idx >= n_in || in_sizes[tracks_idx] < 2 ||
        (in_sizes[tracks_idx] & 1)) {
        for (int i = 0; i < n_in; i++) {
            if (in_sizes[i] > n * 2 && in_sizes[i] < n * n &&
                (in_sizes[i] & 1) == 0) { tracks_idx = i; break; }
        }
    }

    const int m = in_sizes[tracks_idx] / 2;      // M = 8192

    const int* tracks = (const int*)d_in[tracks_idx];
    const int* nimg   = (nimg_idx >= 0) ? (const int*)d_in[nimg_idx] : nullptr;
    float*     out    = (float*)d_out;

    balayer_assoc_kernel<<<1, TPB>>>(tracks, nimg, out, n, m);
}